// round 14
// baseline (speedup 1.0000x reference)
#include <cuda_runtime.h>
#include <stdint.h>

// Problem constants (fixed by the dataset)
#define T_  500
#define B_  16
#define S_  256
#define P_  128
#define L_  16

#define SEG   17     // u32 per p-list: [0] = wordCnt | realCnt<<16; [1..16] packed u8 idx
#define STRF  9      // sl4 stride (float4s) per s: quarter-warp gathers conflict-free
#define OST   129    // output-transpose row stride
#define PADV (-3.402823466e38f)

// Scratch (__device__ globals; allocation is forbidden). Pure fns of inputs.
__device__ uint32_t g_bitsW[L_ * 8 * P_];          // [lang][word][p] membership words
__device__ uint32_t g_list [L_ * P_ * SEG];        // per-p packed u8 lists, FULLY padded
__device__ int      g_rank [L_ * P_];              // [lang][rank] -> p (sorted by count)

// ---------------------------------------------------------------------------
// Stage 1: membership words. CTA = (lang, 32-s chunk) -> 128 CTAs x 256 thr.
// Thread = (p-quad, row-group): 4x LDG.128 (every byte useful), bits combined
// across the 8-lane row groups with shfl-OR; one uint4 store per quad.
// ---------------------------------------------------------------------------
__global__ __launch_bounds__(256) void build_bits_kernel(const float* __restrict__ mats) {
    const int l   = blockIdx.x >> 3;
    const int w   = blockIdx.x & 7;
    const int tid = threadIdx.x;
    const int tq  = tid >> 3;           // 0..31 -> p-quad p4 = tq*4
    const int rr  = tid & 7;            // row group (4 rows each)
    const int p4  = tq * 4;
    const int r0  = w * 32 + rr * 4;

    uint32_t wc0 = 0, wc1 = 0, wc2 = 0, wc3 = 0;
    #pragma unroll
    for (int j = 0; j < 4; ++j) {
        const float4 f = *(const float4*)(mats + ((size_t)l * S_ + r0 + j) * P_ + p4);
        const int bp = rr * 4 + j;
        wc0 |= (f.x != 0.0f ? 1u : 0u) << bp;
        wc1 |= (f.y != 0.0f ? 1u : 0u) << bp;
        wc2 |= (f.z != 0.0f ? 1u : 0u) << bp;
        wc3 |= (f.w != 0.0f ? 1u : 0u) << bp;
    }
    #pragma unroll
    for (int d = 1; d < 8; d <<= 1) {   // OR-combine the 8-lane row groups
        wc0 |= __shfl_xor_sync(0xffffffffu, wc0, d);
        wc1 |= __shfl_xor_sync(0xffffffffu, wc1, d);
        wc2 |= __shfl_xor_sync(0xffffffffu, wc2, d);
        wc3 |= __shfl_xor_sync(0xffffffffu, wc3, d);
    }
    if (rr == 0) {
        uint4 o; o.x = wc0; o.y = wc1; o.z = wc2; o.w = wc3;
        *(uint4*)(g_bitsW + (l * 8 + w) * P_ + p4) = o;   // 16B-aligned (p4 % 4 == 0)
    }
}

// ---------------------------------------------------------------------------
// Stage 2 (fused lists + rank): one CTA per lang, 256 threads = 8 warps.
// Each warp ballot-builds 16 p-lists (lane i owns byte i = s 8i..8i+7):
// popc + shfl-scan -> write offsets; all 64 index bytes written every call
// (real indices then duplicated-last-index padding -> idempotent under max;
// empty list pads 0, fixed by select in main kernel). Then 128 threads
// compute the per-lang count-rank in smem.
// ---------------------------------------------------------------------------
__global__ __launch_bounds__(256) void build_lists_rank_kernel() {
    __shared__ int scnt[P_];
    const int lang = blockIdx.x;
    const int lane = threadIdx.x & 31;
    const int wid  = threadIdx.x >> 5;

    for (int it = 0; it < 16; ++it) {
        const int p = wid * 16 + it;
        uint32_t word = g_bitsW[(lang * 8 + (lane >> 2)) * P_ + p];
        uint32_t byte = (word >> (8 * (lane & 3))) & 255u;
        int cnt = __popc(byte);

        int inc = cnt;                                       // inclusive scan
        #pragma unroll
        for (int d = 1; d < 32; d <<= 1) {
            int o = __shfl_up_sync(0xffffffffu, inc, d);
            if (lane >= d) inc += o;
        }
        const int total = __shfl_sync(0xffffffffu, inc, 31);
        const int base  = inc - cnt;

        int lastidx = cnt ? (lane * 8 + (31 - __clz(byte))) : -1;
        #pragma unroll
        for (int d = 16; d; d >>= 1)
            lastidx = max(lastidx, __shfl_xor_sync(0xffffffffu, lastidx, d));
        const unsigned char fl = (unsigned char)max(lastidx, 0);

        unsigned char* dstb = (unsigned char*)(g_list + ((size_t)lang * P_ + p) * SEG + 1);
        uint32_t bb = byte; int off = base;
        while (bb) {                                         // <=8 iters, mostly <=2
            int j = __ffs(bb) - 1; bb &= bb - 1;
            if (off < 4 * (SEG - 1)) dstb[off] = (unsigned char)(lane * 8 + j);
            ++off;
        }
        const int realc = min(total, 4 * (SEG - 1));
        for (int o = realc + lane; o < 4 * (SEG - 1); o += 32) dstb[o] = fl;  // full pad
        if (lane == 0) {
            const int m = (realc + 3) >> 2;
            g_list[((size_t)lang * P_ + p) * SEG] = (uint32_t)m | ((uint32_t)realc << 16);
            scnt[p] = m;
        }
    }
    __syncthreads();

    if (threadIdx.x < P_) {                                  // per-lang count rank
        const int p = threadIdx.x;
        const int mykey = scnt[p] * 256 + p;                 // distinct keys
        int r = 0;
        #pragma unroll 8
        for (int q = 0; q < P_; ++q) r += (scnt[q] * 256 + q < mykey);
        g_rank[lang * P_ + r] = p;
    }
}

// ---------------------------------------------------------------------------
// Main: CTA = (32-t tile, b) -> 256 CTAs x 1024 threads (32 warps, all 128 p).
// Warp = one RANK-quad (count-adjacent lists -> near-zero quad padding).
// Quarter q -> rank p_loc = wid*4+q; lane slot tl holds 4 t's in a float4.
// Gather loop manually UNROLLED x2 (safe: lists fully padded to 16 words,
// padding is max-idempotent) -> 2 list words + 8 independent LDS.128 in
// flight per iteration. Index decode via single-PRMT __byte_perm.
// ---------------------------------------------------------------------------
__global__ __launch_bounds__(1024, 2) void allophone_map_kernel(
    const float* __restrict__ logits,      // [T, B, S]
    const int*   __restrict__ lang_ids,    // [B]
    float*       __restrict__ out)         // [T, B, P]
{
    __shared__ float4   sl4[S_ * STRF];    // 36,864 B (reused as transpose buffer)
    __shared__ uint32_t slist[P_ * SEG];   //  8,704 B (rank-ordered)
    __shared__ int      sperm[P_];         //    512 B (rank -> real p)

    const int t0    = blockIdx.x * 32;
    const int b     = blockIdx.y;
    const int tid   = threadIdx.x;
    const int lane  = tid & 31;
    const int wid   = tid >> 5;
    const int q     = lane >> 3;           // quarter -> which rank of the quad
    const int tl    = lane & 7;            // t-slot (4 t's per lane)
    const int p_loc = wid * 4 + q;         // RANK index

    const int lang = __ldg(lang_ids + b);

    if (tid < P_) sperm[tid] = __ldg(g_rank + lang * P_ + tid);
    __syncthreads();

    // Copy lists into smem in RANK order (gmem reads L2-hot).
    {
        const uint32_t* src = g_list + (size_t)lang * P_ * SEG;
        for (int i = tid; i < P_ * SEG; i += 1024) {
            int rk = i / SEG, j = i - rk * SEG;
            slist[i] = __ldg(src + sperm[rk] * SEG + j);
        }
    }

    // Fill tile once: 2048 items (s, t-quad), 2 per thread. Uniform fast path
    // for non-tail CTAs (no clamps). STS.128: 8 lanes x 16B = 32 banks/quarter.
    const float* lb = logits + b * S_;
    if (t0 + 32 <= T_) {
        #pragma unroll
        for (int i = 0; i < 2; ++i) {
            int g  = i * 1024 + tid;
            int s  = g & (S_ - 1);
            int tq = g >> 8;
            int ta = t0 + 4 * tq;
            float4 v;
            v.x = lb[(ta + 0) * (B_ * S_) + s];
            v.y = lb[(ta + 1) * (B_ * S_) + s];
            v.z = lb[(ta + 2) * (B_ * S_) + s];
            v.w = lb[(ta + 3) * (B_ * S_) + s];
            sl4[s * STRF + tq] = v;
        }
    } else {
        #pragma unroll
        for (int i = 0; i < 2; ++i) {
            int g  = i * 1024 + tid;
            int s  = g & (S_ - 1);
            int tq = g >> 8;
            int ta = t0 + 4 * tq;
            int c0 = min(ta + 0, T_ - 1);
            int c1 = min(ta + 1, T_ - 1);
            int c2 = min(ta + 2, T_ - 1);
            int c3 = min(ta + 3, T_ - 1);
            float4 v;
            v.x = lb[c0 * (B_ * S_) + s];
            v.y = lb[c1 * (B_ * S_) + s];
            v.z = lb[c2 * (B_ * S_) + s];
            v.w = lb[c3 * (B_ * S_) + s];
            sl4[s * STRF + tq] = v;
        }
    }
    __syncthreads();

    // Gather: warp-uniform, unrolled x2 (even-rounded bound; padded words are
    // in-bounds [index <= 15] and idempotent under max).
    const uint32_t* lw  = slist + p_loc * SEG + 1;
    const uint32_t  hdr = slist[p_loc * SEG];
    const int       realc = (int)(hdr >> 16);
    int nwmax = (int)(hdr & 0xFFFFu);
    nwmax = max(nwmax, __shfl_xor_sync(0xffffffffu, nwmax, 8));
    nwmax = max(nwmax, __shfl_xor_sync(0xffffffffu, nwmax, 16));
    const int nw2 = (nwmax + 1) & ~1;

    float a0 = PADV, a1 = PADV, a2 = PADV, a3 = PADV;
    for (int k = 0; k < nw2; k += 2) {
        const uint32_t w0 = lw[k];
        const uint32_t w1 = lw[k + 1];
        float4 v;
        v = sl4[__byte_perm(w0, 0, 0x4440) * STRF + tl];
        a0 = fmaxf(a0, v.x); a1 = fmaxf(a1, v.y); a2 = fmaxf(a2, v.z); a3 = fmaxf(a3, v.w);
        v = sl4[__byte_perm(w0, 0, 0x4441) * STRF + tl];
        a0 = fmaxf(a0, v.x); a1 = fmaxf(a1, v.y); a2 = fmaxf(a2, v.z); a3 = fmaxf(a3, v.w);
        v = sl4[__byte_perm(w0, 0, 0x4442) * STRF + tl];
        a0 = fmaxf(a0, v.x); a1 = fmaxf(a1, v.y); a2 = fmaxf(a2, v.z); a3 = fmaxf(a3, v.w);
        v = sl4[__byte_perm(w0, 0, 0x4443) * STRF + tl];
        a0 = fmaxf(a0, v.x); a1 = fmaxf(a1, v.y); a2 = fmaxf(a2, v.z); a3 = fmaxf(a3, v.w);
        v = sl4[__byte_perm(w1, 0, 0x4440) * STRF + tl];
        a0 = fmaxf(a0, v.x); a1 = fmaxf(a1, v.y); a2 = fmaxf(a2, v.z); a3 = fmaxf(a3, v.w);
        v = sl4[__byte_perm(w1, 0, 0x4441) * STRF + tl];
        a0 = fmaxf(a0, v.x); a1 = fmaxf(a1, v.y); a2 = fmaxf(a2, v.z); a3 = fmaxf(a3, v.w);
        v = sl4[__byte_perm(w1, 0, 0x4442) * STRF + tl];
        a0 = fmaxf(a0, v.x); a1 = fmaxf(a1, v.y); a2 = fmaxf(a2, v.z); a3 = fmaxf(a3, v.w);
        v = sl4[__byte_perm(w1, 0, 0x4443) * STRF + tl];
        a0 = fmaxf(a0, v.x); a1 = fmaxf(a1, v.y); a2 = fmaxf(a2, v.z); a3 = fmaxf(a3, v.w);
    }
    if (realc == 0) { a0 = a1 = a2 = a3 = PADV; }   // empty-list pad was s=0
    const int realp = sperm[p_loc];
    __syncthreads();                                // all sl4 reads done before reuse

    // Transpose through reused smem (perm resolved here).
    float* so = (float*)sl4;                        // 32*129 floats < capacity
    so[(4 * tl + 0) * OST + realp] = a0;
    so[(4 * tl + 1) * OST + realp] = a1;
    so[(4 * tl + 2) * OST + realp] = a2;
    so[(4 * tl + 3) * OST + realp] = a3;
    __syncthreads();

    // Coalesced stores (128 contiguous p per t-row), tail-guarded.
    #pragma unroll
    for (int i = 0; i < 4; ++i) {
        int g2 = i * 1024 + tid;
        int t  = g2 >> 7;
        int pc = g2 & (P_ - 1);
        int tt = t0 + t;
        if (tt < T_)
            out[(tt * B_ + b) * P_ + pc] = so[t * OST + pc];
    }
}

// ---------------------------------------------------------------------------
extern "C" void kernel_launch(void* const* d_in, const int* in_sizes, int n_in,
                              void* d_out, int out_size) {
    const float* logits = (const float*)d_in[0];   // [T,B,S] f32
    const int*   langs  = (const int*)  d_in[1];   // [B] i32
    const float* mats   = (const float*)d_in[2];   // [L,S,P] f32
    // d_in[3] (mask) is redundant: mask == (mats == 0)

    build_bits_kernel      <<<L_ * 8, 256>>>(mats);   // 128 CTAs, float4 loads
    build_lists_rank_kernel<<<L_, 256>>>();           // 16 CTAs (lists + rank fused)

    dim3 grid(16, B_);                                // 256 CTAs x 1024 threads
    allophone_map_kernel<<<grid, 1024>>>(logits, langs, (float*)d_out);
}

// round 15
// speedup vs baseline: 1.3695x; 1.3695x over previous
#include <cuda_runtime.h>
#include <stdint.h>

// Problem constants (fixed by the dataset)
#define T_  500
#define B_  16
#define S_  256
#define P_  128
#define L_  16

#define SEG   17     // u32 per p-list: [0] = wordCnt | realCnt<<16; [1..16] packed u8 idx
#define STRF  9      // sl4 stride (float4s) per s: quarter-warp gathers conflict-free
#define OST   129    // output-transpose row stride
#define PADV (-3.402823466e38f)

// Scratch (__device__ globals; allocation is forbidden). Pure fns of inputs.
__device__ uint32_t g_list[L_ * P_ * SEG];   // per-p packed u8 lists, FULLY padded
__device__ int      g_rank[L_ * P_];         // [lang][rank] -> p (sorted by count)

// ---------------------------------------------------------------------------
// Fused build: ONE launch. CTA = lang (16 CTAs x 1024 threads).
// Phase 1: thread (w = tid>>7, p = tid&127) builds membership word w for p
//          from 32 independent coalesced loads (MLP 32, L2-hot on replay).
// Phase 2: warp-per-p ballot list builder (4 serial p's per warp): popc +
//          shfl-scan -> write offsets; all 64 index bytes written (real
//          indices then duplicated-last-index padding -> idempotent under
//          max; empty list pads 0, fixed by select in main kernel).
// Phase 3: 128 threads compute per-lang count rank (distinct keys).
// ---------------------------------------------------------------------------
__global__ __launch_bounds__(1024) void build_all_kernel(const float* __restrict__ mats) {
    __shared__ uint32_t sbits[8 * P_];   // [w][p]
    __shared__ int      scnt[P_];

    const int lang = blockIdx.x;
    const int tid  = threadIdx.x;

    // Phase 1: bits straight to smem.
    {
        const int p = tid & (P_ - 1);
        const int w = tid >> 7;                       // 0..7
        const float* base = mats + ((size_t)lang * S_ + w * 32) * P_ + p;
        uint32_t word = 0;
        #pragma unroll
        for (int j = 0; j < 32; ++j) {
            float v = base[(size_t)j * P_];           // coalesced across p
            word |= (v != 0.0f ? 1u : 0u) << j;
        }
        sbits[w * P_ + p] = word;
    }
    __syncthreads();

    // Phase 2: ballot list builder, warp i handles p = it*32 + i.
    const int lane = tid & 31;
    const int wid  = tid >> 5;
    #pragma unroll
    for (int it = 0; it < 4; ++it) {
        const int p = it * 32 + wid;
        uint32_t word = sbits[(lane >> 2) * P_ + p];  // 4 lanes share a word
        uint32_t byte = (word >> (8 * (lane & 3))) & 255u;
        int cnt = __popc(byte);

        int inc = cnt;                                // inclusive scan
        #pragma unroll
        for (int d = 1; d < 32; d <<= 1) {
            int o = __shfl_up_sync(0xffffffffu, inc, d);
            if (lane >= d) inc += o;
        }
        const int total = __shfl_sync(0xffffffffu, inc, 31);
        const int base  = inc - cnt;

        int lastidx = cnt ? (lane * 8 + (31 - __clz(byte))) : -1;
        #pragma unroll
        for (int d = 16; d; d >>= 1)
            lastidx = max(lastidx, __shfl_xor_sync(0xffffffffu, lastidx, d));
        const unsigned char fl = (unsigned char)max(lastidx, 0);

        unsigned char* dstb = (unsigned char*)(g_list + ((size_t)lang * P_ + p) * SEG + 1);
        uint32_t bb = byte; int off = base;
        while (bb) {                                  // <=8 iters, mostly <=2
            int j = __ffs(bb) - 1; bb &= bb - 1;
            if (off < 4 * (SEG - 1)) dstb[off] = (unsigned char)(lane * 8 + j);
            ++off;
        }
        const int realc = min(total, 4 * (SEG - 1));
        for (int o = realc + lane; o < 4 * (SEG - 1); o += 32) dstb[o] = fl;  // full pad
        if (lane == 0) {
            const int m = (realc + 3) >> 2;
            g_list[((size_t)lang * P_ + p) * SEG] = (uint32_t)m | ((uint32_t)realc << 16);
            scnt[p] = m;
        }
    }
    __syncthreads();

    // Phase 3: count rank (stable via distinct keys).
    if (tid < P_) {
        const int p = tid;
        const int mykey = scnt[p] * 256 + p;
        int r = 0;
        #pragma unroll 8
        for (int q = 0; q < P_; ++q) r += (scnt[q] * 256 + q < mykey);
        g_rank[lang * P_ + r] = p;
    }
}

// ---------------------------------------------------------------------------
// Main (VERBATIM R13 structure — measured 12.1us):
// CTA = (32-t tile, b) -> 256 CTAs x 1024 threads (32 warps, all 128 p).
// Warp = one RANK-quad (count-adjacent lists -> near-zero quad padding).
// Quarter q -> rank p_loc = wid*4+q; lane slot tl holds 4 t's in a float4;
// each gather iteration: 4 LDS.128 serve 512 updates at the conflict floor.
// Lists fully padded -> reading past own count is a max-idempotent no-op.
// ---------------------------------------------------------------------------
__global__ __launch_bounds__(1024, 2) void allophone_map_kernel(
    const float* __restrict__ logits,      // [T, B, S]
    const int*   __restrict__ lang_ids,    // [B]
    float*       __restrict__ out)         // [T, B, P]
{
    __shared__ float4   sl4[S_ * STRF];    // 36,864 B (reused as transpose buffer)
    __shared__ uint32_t slist[P_ * SEG];   //  8,704 B (rank-ordered)
    __shared__ int      sperm[P_];         //    512 B (rank -> real p)

    const int t0    = blockIdx.x * 32;
    const int b     = blockIdx.y;
    const int tid   = threadIdx.x;
    const int lane  = tid & 31;
    const int wid   = tid >> 5;
    const int q     = lane >> 3;           // quarter -> which rank of the quad
    const int tl    = lane & 7;            // t-slot (4 t's per lane)
    const int p_loc = wid * 4 + q;         // RANK index

    const int lang = __ldg(lang_ids + b);

    if (tid < P_) sperm[tid] = __ldg(g_rank + lang * P_ + tid);
    __syncthreads();

    // Copy lists into smem in RANK order (gmem reads L2-hot).
    {
        const uint32_t* src = g_list + (size_t)lang * P_ * SEG;
        for (int i = tid; i < P_ * SEG; i += 1024) {
            int rk = i / SEG, j = i - rk * SEG;
            slist[i] = __ldg(src + sperm[rk] * SEG + j);
        }
    }

    // Fill tile once: 2048 items (s, t-quad), 2 per thread. 4 coalesced LDG.32
    // + one STS.128; 8 lanes x 16B = all 32 banks per quarter: conflict-free.
    const float* lb = logits + b * S_;
    #pragma unroll
    for (int i = 0; i < 2; ++i) {
        int g  = i * 1024 + tid;
        int s  = g & (S_ - 1);
        int tq = g >> 8;                   // 0..7
        int ta = t0 + 4 * tq;
        int c0 = min(ta + 0, T_ - 1);      // tail clamp (stores guarded below)
        int c1 = min(ta + 1, T_ - 1);
        int c2 = min(ta + 2, T_ - 1);
        int c3 = min(ta + 3, T_ - 1);
        float4 v;
        v.x = lb[c0 * (B_ * S_) + s];
        v.y = lb[c1 * (B_ * S_) + s];
        v.z = lb[c2 * (B_ * S_) + s];
        v.w = lb[c3 * (B_ * S_) + s];
        sl4[s * STRF + tq] = v;
    }
    __syncthreads();

    // Gather: warp-uniform loop to quad-max count (~= own count after sorting).
    const uint32_t* lw  = slist + p_loc * SEG + 1;
    const uint32_t  hdr = slist[p_loc * SEG];
    const int       realc = (int)(hdr >> 16);
    int nwmax = (int)(hdr & 0xFFFFu);
    nwmax = max(nwmax, __shfl_xor_sync(0xffffffffu, nwmax, 8));
    nwmax = max(nwmax, __shfl_xor_sync(0xffffffffu, nwmax, 16));

    float a0 = PADV, a1 = PADV, a2 = PADV, a3 = PADV;
    for (int k = 0; k < nwmax; ++k) {
        uint32_t w = lw[k];                // fully padded: safe & idempotent past own count
        float4 v;
        v = sl4[(w         & 255u) * STRF + tl];
        a0 = fmaxf(a0, v.x); a1 = fmaxf(a1, v.y); a2 = fmaxf(a2, v.z); a3 = fmaxf(a3, v.w);
        v = sl4[((w >>  8) & 255u) * STRF + tl];
        a0 = fmaxf(a0, v.x); a1 = fmaxf(a1, v.y); a2 = fmaxf(a2, v.z); a3 = fmaxf(a3, v.w);
        v = sl4[((w >> 16) & 255u) * STRF + tl];
        a0 = fmaxf(a0, v.x); a1 = fmaxf(a1, v.y); a2 = fmaxf(a2, v.z); a3 = fmaxf(a3, v.w);
        v = sl4[( w >> 24        ) * STRF + tl];
        a0 = fmaxf(a0, v.x); a1 = fmaxf(a1, v.y); a2 = fmaxf(a2, v.z); a3 = fmaxf(a3, v.w);
    }
    if (realc == 0) { a0 = a1 = a2 = a3 = PADV; }   // empty-list pad was s=0
    const int realp = sperm[p_loc];
    __syncthreads();                                // all sl4 reads done before reuse

    // Transpose through reused smem (perm resolved here; few-wavefront cost).
    float* so = (float*)sl4;                        // 32*129 floats < capacity
    so[(4 * tl + 0) * OST + realp] = a0;
    so[(4 * tl + 1) * OST + realp] = a1;
    so[(4 * tl + 2) * OST + realp] = a2;
    so[(4 * tl + 3) * OST + realp] = a3;
    __syncthreads();

    // Coalesced stores (128 contiguous p per t-row), tail-guarded.
    #pragma unroll
    for (int i = 0; i < 4; ++i) {
        int g2 = i * 1024 + tid;
        int t  = g2 >> 7;
        int pc = g2 & (P_ - 1);
        int tt = t0 + t;
        if (tt < T_)
            out[(tt * B_ + b) * P_ + pc] = so[t * OST + pc];
    }
}

// ---------------------------------------------------------------------------
extern "C" void kernel_launch(void* const* d_in, const int* in_sizes, int n_in,
                              void* d_out, int out_size) {
    const float* logits = (const float*)d_in[0];   // [T,B,S] f32
    const int*   langs  = (const int*)  d_in[1];   // [B] i32
    const float* mats   = (const float*)d_in[2];   // [L,S,P] f32
    // d_in[3] (mask) is redundant: mask == (mats == 0)

    build_all_kernel<<<L_, 1024>>>(mats);          // 16 CTAs, ONE build launch

    dim3 grid(16, B_);                             // 256 CTAs x 1024 threads
    allophone_map_kernel<<<grid, 1024>>>(logits, langs, (float*)d_out);
}

// round 16
// speedup vs baseline: 1.5977x; 1.1667x over previous
#include <cuda_runtime.h>
#include <stdint.h>

// Problem constants (fixed by the dataset)
#define T_  500
#define B_  16
#define S_  256
#define P_  128
#define L_  16

#define SEG   17     // u32 per p-list: [0] = wordCnt | realCnt<<16; [1..16] packed u8 idx
#define STRF  9      // sl4 stride (float4s) per s: quarter-warp gathers conflict-free
#define OST   129    // output-transpose row stride
#define PADV (-3.402823466e38f)

// Scratch (__device__ globals; allocation is forbidden). Pure fns of inputs.
__device__ uint32_t g_list[L_ * P_ * SEG];   // per-p packed u8 lists, FULLY padded to 64B
__device__ int      g_cnt [L_ * P_];         // per-p word count (dense, for in-main rank)

// ---------------------------------------------------------------------------
// ONE wide build launch: CTA = (lang, 8-p group) -> 256 CTAs x 128 threads.
// Phase A: thread (rr = tid>>3, j = tid&7) builds halfword rr (16 consecutive
//          s) of p = p0+j from 16 coalesced loads -> smem. No transpose.
// Phase B: warp wi compacts 2 p's with the popc-prefix trick (no shfl
//          chains): per 32-bit word, pos = tot + popc(word & lanemask_lt);
//          set bits store s directly as bytes to g_list. Lists fully padded
//          to 64 bytes with the last index (idempotent under max; empty
//          list pads 0, fixed by select in main). Counts -> g_cnt.
// Wide grid + short dependency chains: prologue-class ~1-2us.
// ---------------------------------------------------------------------------
__global__ __launch_bounds__(128) void build_kernel(const float* __restrict__ mats) {
    __shared__ unsigned short sh16[8 * 16];   // [j][rr] halfwords

    const int l  = blockIdx.x >> 4;
    const int g  = blockIdx.x & 15;
    const int p0 = g * 8;
    const int tid  = threadIdx.x;
    const int rr   = tid >> 3;                // 0..15: 16-row block
    const int j    = tid & 7;                 // 0..7: p offset

    // Phase A: halfword for s in [rr*16, rr*16+16), column p0+j.
    const float* base = mats + ((size_t)l * S_ + rr * 16) * P_ + p0 + j;
    uint32_t hw = 0;
    #pragma unroll
    for (int i = 0; i < 16; ++i) {
        float v = base[(size_t)i * P_];       // 4 sectors per warp-load, fine
        hw |= (v != 0.0f ? 1u : 0u) << i;
    }
    sh16[j * 16 + rr] = (unsigned short)hw;
    __syncthreads();

    // Phase B: warp wi handles p = p0 + 2*wi and p0 + 2*wi + 1.
    const int lane = tid & 31;
    const int wi   = tid >> 5;
    const uint32_t lmask = (1u << lane) - 1u;

    #pragma unroll
    for (int half = 0; half < 2; ++half) {
        const int jj = 2 * wi + half;
        const int p  = p0 + jj;
        unsigned char* dstb =
            (unsigned char*)(g_list + ((size_t)l * P_ + p) * SEG + 1);

        int tot = 0, fl_s = 0;
        #pragma unroll
        for (int w = 0; w < 8; ++w) {
            uint32_t word = (uint32_t)sh16[jj * 16 + 2 * w]
                          | ((uint32_t)sh16[jj * 16 + 2 * w + 1] << 16);
            int pos = tot + __popc(word & lmask);
            if (((word >> lane) & 1u) && pos < 64)
                dstb[pos] = (unsigned char)(w * 32 + lane);
            tot += __popc(word);
            if (word) fl_s = w * 32 + (31 - __clz(word));
        }
        const int realc = min(tot, 64);
        const unsigned char fl = (unsigned char)fl_s;     // 0 if empty (realc==0)
        for (int o = realc + lane; o < 64; o += 32) dstb[o] = fl;  // FULL pad
        if (lane == 0) {
            const int m = (realc + 3) >> 2;
            g_list[((size_t)l * P_ + p) * SEG] = (uint32_t)m | ((uint32_t)realc << 16);
            g_cnt[l * P_ + p] = m;
        }
    }
}

// ---------------------------------------------------------------------------
// Main (R13 gather engine, measured 12.1us, + in-main rank):
// CTA = (32-t tile, b) -> 256 CTAs x 1024 threads (32 warps, all 128 p).
// Warp = one RANK-quad via sperm indirection (count-adjacent lists -> near-
// zero quad padding). Quarter q -> rank p_loc = wid*4+q; lane slot tl holds
// 4 t's in a float4; each gather iteration: 4 LDS.128 serve 512 updates at
// the conflict floor. Lists fully padded -> safe past own count.
// ---------------------------------------------------------------------------
__global__ __launch_bounds__(1024, 2) void allophone_map_kernel(
    const float* __restrict__ logits,      // [T, B, S]
    const int*   __restrict__ lang_ids,    // [B]
    float*       __restrict__ out)         // [T, B, P]
{
    __shared__ float4   sl4[S_ * STRF];    // 36,864 B (reused as transpose buffer)
    __shared__ uint32_t slist[P_ * SEG];   //  8,704 B (RAW order; perm at gather)
    __shared__ int      scnt[P_];          //    512 B
    __shared__ int      sperm[P_];         //    512 B (rank -> real p)

    const int t0    = blockIdx.x * 32;
    const int b     = blockIdx.y;
    const int tid   = threadIdx.x;
    const int lane  = tid & 31;
    const int wid   = tid >> 5;
    const int q     = lane >> 3;           // quarter -> which rank of the quad
    const int tl    = lane & 7;            // t-slot (4 t's per lane)
    const int p_loc = wid * 4 + q;         // RANK index

    const int lang = __ldg(lang_ids + b);

    // Counts (coalesced, L2-hot) + raw-order list copy + tile fill — all
    // independent, overlap freely before the first sync.
    if (tid < P_) scnt[tid] = __ldg(g_cnt + lang * P_ + tid);
    {
        const uint32_t* src = g_list + (size_t)lang * P_ * SEG;
        for (int i = tid; i < P_ * SEG; i += 1024) slist[i] = __ldg(src + i);
    }
    const float* lb = logits + b * S_;
    #pragma unroll
    for (int i = 0; i < 2; ++i) {
        int gg = i * 1024 + tid;
        int s  = gg & (S_ - 1);
        int tq = gg >> 8;                  // 0..7
        int ta = t0 + 4 * tq;
        int c0 = min(ta + 0, T_ - 1);      // tail clamp (stores guarded below)
        int c1 = min(ta + 1, T_ - 1);
        int c2 = min(ta + 2, T_ - 1);
        int c3 = min(ta + 3, T_ - 1);
        float4 v;
        v.x = lb[c0 * (B_ * S_) + s];
        v.y = lb[c1 * (B_ * S_) + s];
        v.z = lb[c2 * (B_ * S_) + s];
        v.w = lb[c3 * (B_ * S_) + s];
        sl4[s * STRF + tq] = v;
    }
    __syncthreads();

    // In-main rank (128 threads, ~500 cyc; hidden by the co-resident CTA).
    if (tid < P_) {
        const int p = tid;
        const int mykey = scnt[p] * 256 + p;        // distinct keys -> permutation
        int r = 0;
        #pragma unroll 8
        for (int qq = 0; qq < P_; ++qq) r += (scnt[qq] * 256 + qq < mykey);
        sperm[r] = p;
    }
    __syncthreads();

    // Gather: warp-uniform loop to quad-max count (~= own count after rank).
    const int       p_s = sperm[p_loc];             // quarter-uniform broadcast
    const uint32_t* lw  = slist + p_s * SEG + 1;
    const uint32_t  hdr = slist[p_s * SEG];
    const int       realc = (int)(hdr >> 16);
    int nwmax = (int)(hdr & 0xFFFFu);
    nwmax = max(nwmax, __shfl_xor_sync(0xffffffffu, nwmax, 8));
    nwmax = max(nwmax, __shfl_xor_sync(0xffffffffu, nwmax, 16));

    float a0 = PADV, a1 = PADV, a2 = PADV, a3 = PADV;
    for (int k = 0; k < nwmax; ++k) {
        uint32_t w = lw[k];                // fully padded: safe & idempotent past own count
        float4 v;
        v = sl4[(w         & 255u) * STRF + tl];
        a0 = fmaxf(a0, v.x); a1 = fmaxf(a1, v.y); a2 = fmaxf(a2, v.z); a3 = fmaxf(a3, v.w);
        v = sl4[((w >>  8) & 255u) * STRF + tl];
        a0 = fmaxf(a0, v.x); a1 = fmaxf(a1, v.y); a2 = fmaxf(a2, v.z); a3 = fmaxf(a3, v.w);
        v = sl4[((w >> 16) & 255u) * STRF + tl];
        a0 = fmaxf(a0, v.x); a1 = fmaxf(a1, v.y); a2 = fmaxf(a2, v.z); a3 = fmaxf(a3, v.w);
        v = sl4[( w >> 24        ) * STRF + tl];
        a0 = fmaxf(a0, v.x); a1 = fmaxf(a1, v.y); a2 = fmaxf(a2, v.z); a3 = fmaxf(a3, v.w);
    }
    if (realc == 0) { a0 = a1 = a2 = a3 = PADV; }   // empty-list pad was s=0
    __syncthreads();                                // all sl4 reads done before reuse

    // Transpose through reused smem (perm resolved here; few-wavefront cost).
    float* so = (float*)sl4;                        // 32*129 floats < capacity
    so[(4 * tl + 0) * OST + p_s] = a0;
    so[(4 * tl + 1) * OST + p_s] = a1;
    so[(4 * tl + 2) * OST + p_s] = a2;
    so[(4 * tl + 3) * OST + p_s] = a3;
    __syncthreads();

    // Coalesced stores (128 contiguous p per t-row), tail-guarded.
    #pragma unroll
    for (int i = 0; i < 4; ++i) {
        int g2 = i * 1024 + tid;
        int t  = g2 >> 7;
        int pc = g2 & (P_ - 1);
        int tt = t0 + t;
        if (tt < T_)
            out[(tt * B_ + b) * P_ + pc] = so[t * OST + pc];
    }
}

// ---------------------------------------------------------------------------
extern "C" void kernel_launch(void* const* d_in, const int* in_sizes, int n_in,
                              void* d_out, int out_size) {
    const float* logits = (const float*)d_in[0];   // [T,B,S] f32
    const int*   langs  = (const int*)  d_in[1];   // [B] i32
    const float* mats   = (const float*)d_in[2];   // [L,S,P] f32
    // d_in[3] (mask) is redundant: mask == (mats == 0)

    build_kernel<<<L_ * 16, 128>>>(mats);          // 256 CTAs, ONE wide build launch

    dim3 grid(16, B_);                             // 256 CTAs x 1024 threads
    allophone_map_kernel<<<grid, 1024>>>(logits, langs, (float*)d_out);
}

// round 17
// speedup vs baseline: 1.8052x; 1.1299x over previous
#include <cuda_runtime.h>
#include <stdint.h>

// Problem constants (fixed by the dataset)
#define T_  500
#define B_  16
#define S_  256
#define P_  128
#define L_  16

#define SEG   17     // u32 per p-list: [0] = wordCnt | realCnt<<16; [1..16] packed u8 idx
#define STRF  9      // sl4 stride (float4s) per s: quarter-warp gathers conflict-free
#define OST   129    // output-transpose row stride
#define PADV (-3.402823466e38f)

// Scratch (__device__ globals; allocation is forbidden). Pure fns of inputs.
__device__ uint32_t g_list[L_ * P_ * SEG];   // per-p packed u8 lists, FULLY padded to 64B
__device__ int      g_cnt [L_ * P_];         // per-p word count (dense, for in-main rank)

// ---------------------------------------------------------------------------
// ONE wide build launch (verbatim R16, measured within rest=3.1us):
// CTA = (lang, 8-p group) -> 256 CTAs x 128 threads.
// Phase A: halfwords via 16 coalesced loads; Phase B: warp popc-prefix
// compaction, fully padded lists (max-idempotent; empty pads 0).
// ---------------------------------------------------------------------------
__global__ __launch_bounds__(128) void build_kernel(const float* __restrict__ mats) {
    __shared__ unsigned short sh16[8 * 16];   // [j][rr] halfwords

    const int l  = blockIdx.x >> 4;
    const int g  = blockIdx.x & 15;
    const int p0 = g * 8;
    const int tid  = threadIdx.x;
    const int rr   = tid >> 3;                // 0..15: 16-row block
    const int j    = tid & 7;                 // 0..7: p offset

    const float* base = mats + ((size_t)l * S_ + rr * 16) * P_ + p0 + j;
    uint32_t hw = 0;
    #pragma unroll
    for (int i = 0; i < 16; ++i) {
        float v = base[(size_t)i * P_];
        hw |= (v != 0.0f ? 1u : 0u) << i;
    }
    sh16[j * 16 + rr] = (unsigned short)hw;
    __syncthreads();

    const int lane = tid & 31;
    const int wi   = tid >> 5;
    const uint32_t lmask = (1u << lane) - 1u;

    #pragma unroll
    for (int half = 0; half < 2; ++half) {
        const int jj = 2 * wi + half;
        const int p  = p0 + jj;
        unsigned char* dstb =
            (unsigned char*)(g_list + ((size_t)l * P_ + p) * SEG + 1);

        int tot = 0, fl_s = 0;
        #pragma unroll
        for (int w = 0; w < 8; ++w) {
            uint32_t word = (uint32_t)sh16[jj * 16 + 2 * w]
                          | ((uint32_t)sh16[jj * 16 + 2 * w + 1] << 16);
            int pos = tot + __popc(word & lmask);
            if (((word >> lane) & 1u) && pos < 64)
                dstb[pos] = (unsigned char)(w * 32 + lane);
            tot += __popc(word);
            if (word) fl_s = w * 32 + (31 - __clz(word));
        }
        const int realc = min(tot, 64);
        const unsigned char fl = (unsigned char)fl_s;     // 0 if empty (realc==0)
        for (int o = realc + lane; o < 64; o += 32) dstb[o] = fl;  // FULL pad
        if (lane == 0) {
            const int m = (realc + 3) >> 2;
            g_list[((size_t)l * P_ + p) * SEG] = (uint32_t)m | ((uint32_t)realc << 16);
            g_cnt[l * P_ + p] = m;
        }
    }
}

// ---------------------------------------------------------------------------
// Main: CTA = (32-t tile, b) -> 256 CTAs x 1024 threads (32 warps, all 128 p).
// WARP-SPECIALIZED prologue: warps 0-3 load counts + rank (named barrier 1,
// 128 threads) while warps 4-31 copy lists + fill the tile -> rank is OFF the
// critical path. Gather (R13 engine): warp = RANK-quad via sperm indirection,
// quarter q -> rank wid*4+q, lane slot tl holds 4 t's (float4); 4 LDS.128 per
// word serve 512 updates at the conflict floor; #pragma unroll 2 for MLP.
// ---------------------------------------------------------------------------
__global__ __launch_bounds__(1024, 2) void allophone_map_kernel(
    const float* __restrict__ logits,      // [T, B, S]
    const int*   __restrict__ lang_ids,    // [B]
    float*       __restrict__ out)         // [T, B, P]
{
    __shared__ float4   sl4[S_ * STRF];    // 36,864 B (reused as transpose buffer)
    __shared__ uint32_t slist[P_ * SEG];   //  8,704 B (RAW order; perm at gather)
    __shared__ int      scnt[P_];          //    512 B
    __shared__ int      sperm[P_];         //    512 B (rank -> real p)

    const int t0    = blockIdx.x * 32;
    const int b     = blockIdx.y;
    const int tid   = threadIdx.x;
    const int lane  = tid & 31;
    const int wid   = tid >> 5;
    const int q     = lane >> 3;           // quarter -> which rank of the quad
    const int tl    = lane & 7;            // t-slot (4 t's per lane)
    const int p_loc = wid * 4 + q;         // RANK index

    const int lang = __ldg(lang_ids + b);

    if (tid < P_) {
        // ---- rank crew (warps 0-3): counts -> named barrier -> rank ----
        scnt[tid] = __ldg(g_cnt + lang * P_ + tid);
        asm volatile("bar.sync 1, 128;" ::: "memory");
        const int p = tid;
        const int mykey = scnt[p] * 256 + p;            // distinct keys -> permutation
        int r = 0;
        #pragma unroll 8
        for (int qq = 0; qq < P_; ++qq) r += (scnt[qq] * 256 + qq < mykey);
        sperm[r] = p;
    } else {
        // ---- fill crew (warps 4-31, 896 threads): list copy + tile fill ----
        const int ftid = tid - P_;                      // 0..895
        const uint32_t* src = g_list + (size_t)lang * P_ * SEG;
        for (int i = ftid; i < P_ * SEG; i += 896) slist[i] = __ldg(src + i);

        const float* lb = logits + b * S_;
        for (int i = ftid; i < 2048; i += 896) {
            int s  = i & (S_ - 1);
            int tq = i >> 8;               // 0..7
            int ta = t0 + 4 * tq;
            int c0 = min(ta + 0, T_ - 1);  // tail clamp (stores guarded below)
            int c1 = min(ta + 1, T_ - 1);
            int c2 = min(ta + 2, T_ - 1);
            int c3 = min(ta + 3, T_ - 1);
            float4 v;
            v.x = lb[c0 * (B_ * S_) + s];
            v.y = lb[c1 * (B_ * S_) + s];
            v.z = lb[c2 * (B_ * S_) + s];
            v.w = lb[c3 * (B_ * S_) + s];
            sl4[s * STRF + tq] = v;
        }
    }
    __syncthreads();

    // Gather: warp-uniform loop to quad-max count (~= own count after rank).
    const int       p_s = sperm[p_loc];             // quarter-uniform broadcast
    const uint32_t* lw  = slist + p_s * SEG + 1;
    const uint32_t  hdr = slist[p_s * SEG];
    const int       realc = (int)(hdr >> 16);
    int nwmax = (int)(hdr & 0xFFFFu);
    nwmax = max(nwmax, __shfl_xor_sync(0xffffffffu, nwmax, 8));
    nwmax = max(nwmax, __shfl_xor_sync(0xffffffffu, nwmax, 16));

    float a0 = PADV, a1 = PADV, a2 = PADV, a3 = PADV;
    #pragma unroll 2
    for (int k = 0; k < nwmax; ++k) {
        uint32_t w = lw[k];                // fully padded: safe & idempotent past own count
        float4 v;
        v = sl4[(w         & 255u) * STRF + tl];
        a0 = fmaxf(a0, v.x); a1 = fmaxf(a1, v.y); a2 = fmaxf(a2, v.z); a3 = fmaxf(a3, v.w);
        v = sl4[((w >>  8) & 255u) * STRF + tl];
        a0 = fmaxf(a0, v.x); a1 = fmaxf(a1, v.y); a2 = fmaxf(a2, v.z); a3 = fmaxf(a3, v.w);
        v = sl4[((w >> 16) & 255u) * STRF + tl];
        a0 = fmaxf(a0, v.x); a1 = fmaxf(a1, v.y); a2 = fmaxf(a2, v.z); a3 = fmaxf(a3, v.w);
        v = sl4[( w >> 24        ) * STRF + tl];
        a0 = fmaxf(a0, v.x); a1 = fmaxf(a1, v.y); a2 = fmaxf(a2, v.z); a3 = fmaxf(a3, v.w);
    }
    if (realc == 0) { a0 = a1 = a2 = a3 = PADV; }   // empty-list pad was s=0
    __syncthreads();                                // all sl4 reads done before reuse

    // Transpose through reused smem (perm resolved here; few-wavefront cost).
    float* so = (float*)sl4;                        // 32*129 floats < capacity
    so[(4 * tl + 0) * OST + p_s] = a0;
    so[(4 * tl + 1) * OST + p_s] = a1;
    so[(4 * tl + 2) * OST + p_s] = a2;
    so[(4 * tl + 3) * OST + p_s] = a3;
    __syncthreads();

    // Coalesced stores (128 contiguous p per t-row), tail-guarded.
    #pragma unroll
    for (int i = 0; i < 4; ++i) {
        int g2 = i * 1024 + tid;
        int t  = g2 >> 7;
        int pc = g2 & (P_ - 1);
        int tt = t0 + t;
        if (tt < T_)
            out[(tt * B_ + b) * P_ + pc] = so[t * OST + pc];
    }
}

// ---------------------------------------------------------------------------
extern "C" void kernel_launch(void* const* d_in, const int* in_sizes, int n_in,
                              void* d_out, int out_size) {
    const float* logits = (const float*)d_in[0];   // [T,B,S] f32
    const int*   langs  = (const int*)  d_in[1];   // [B] i32
    const float* mats   = (const float*)d_in[2];   // [L,S,P] f32
    // d_in[3] (mask) is redundant: mask == (mats == 0)

    build_kernel<<<L_ * 16, 128>>>(mats);          // 256 CTAs, ONE wide build launch

    dim3 grid(16, B_);                             // 256 CTAs x 1024 threads
    allophone_map_kernel<<<grid, 1024>>>(logits, langs, (float*)d_out);
}